// round 15
// baseline (speedup 1.0000x reference)
#include <cuda_runtime.h>
#include <cstdint>

#define NB 8192
#define ND 128
#define NC 256
#define NTD 64                  // 128-wide blocks per dimension
#define NTRI (NTD * (NTD + 1) / 2)   // 2080 upper-triangle tiles
#define TILE_BYTES 65536        // 128x128 fp32
#define CM_BYTES 2048           // 128 float4 meta
#define THREADS 512

// ---------------- device scratch ----------------
__device__ float    g_A[NB * ND];    // A frags: [blk128][band4(32r)][ks16][mt2][lane32][4]
__device__ float    g_B[NB * ND];    // B frags: [blk128][ks16][cb4][ntp2][lane32][4]
__device__ float4   g_meta[NB];      // {p, sq, label_f, 0}
__device__ int      g_lab[NB];
__device__ unsigned g_pos[NB];
__device__ unsigned g_neg[NB];
__device__ int      g_cnt[NC];
__device__ int      g_done;
__device__ int      g_is64;

// ---------------- PTX helpers ----------------
__device__ __forceinline__ uint32_t smem_u32(const void* p) {
    uint32_t a;
    asm("{ .reg .u64 t; cvta.to.shared.u64 t, %1; cvt.u32.u64 %0, t; }" : "=r"(a) : "l"(p));
    return a;
}
#define MBAR_INIT(addr, cnt) \
    asm volatile("mbarrier.init.shared.b64 [%0], %1;" :: "r"(addr), "r"(cnt) : "memory")
#define MBAR_EXPECT_TX(addr, bytes) \
    asm volatile("mbarrier.arrive.expect_tx.shared.b64 _, [%0], %1;" :: "r"(addr), "r"(bytes) : "memory")
#define MBAR_WAIT(addr, ph) do { \
    asm volatile("{\n\t.reg .pred P;\n\tWL_%=:\n\t" \
        "mbarrier.try_wait.parity.acquire.cta.shared::cta.b64 P, [%0], %1, 0x989680;\n\t" \
        "@!P bra WL_%=;\n\t}" :: "r"(addr), "r"(ph) : "memory"); \
} while (0)
#define BULK_G2S(dst, src, bytes, mbar) \
    asm volatile("cp.async.bulk.shared::cluster.global.mbarrier::complete_tx::bytes [%0], [%1], %2, [%3];" \
        :: "r"(dst), "l"(src), "r"(bytes), "r"(mbar) : "memory")
#define BAR_ARRIVE(id) \
    asm volatile("bar.arrive %0, %1;" :: "r"(id), "r"(THREADS) : "memory")
#define BAR_SYNC(id) \
    asm volatile("bar.sync %0, %1;" :: "r"(id), "r"(THREADS) : "memory")

#define MMA_TF32(acc, a, b0, b1) \
    asm volatile("mma.sync.aligned.m16n8k8.row.col.f32.tf32.tf32.f32 " \
        "{%0,%1,%2,%3},{%4,%5,%6,%7},{%8,%9},{%0,%1,%2,%3};" \
        : "+f"((acc)[0]), "+f"((acc)[1]), "+f"((acc)[2]), "+f"((acc)[3]) \
        : "r"(a##0), "r"(a##1), "r"(a##2), "r"(a##3), "r"(b0), "r"(b1))

// ---------------- init: g_cnt/scalars + label-width detect (1 block) ------
__global__ void init_kernel(const int* __restrict__ w) {
    int i = threadIdx.x;
    if (i < NC) g_cnt[i] = 0;
    if (i == 0) g_done = 0;
    if (i < 32) {
        int nz = 0;
        for (int k = i; k < 64; k += 32) nz |= (w[2 * k + 1] != 0);
        nz = __any_sync(0xffffffffu, nz);
        if (i == 0) g_is64 = nz ? 0 : 1;
    }
}

// ---------------- prep: norms/meta/frag stores + pos/neg init -------------
__global__ void prep_kernel(const float* __restrict__ x, const void* __restrict__ labraw) {
    int m = (blockIdx.x * blockDim.x + threadIdx.x) >> 5;
    int l = threadIdx.x & 31;
    if (m >= NB) return;
    float4 v = reinterpret_cast<const float4*>(x)[m * 32 + l];
    float s = v.x * v.x + v.y * v.y + v.z * v.z + v.w * v.w;
    #pragma unroll
    for (int o = 16; o; o >>= 1) s += __shfl_xor_sync(0xffffffffu, s, o);

    float c4[4];
    asm("cvt.rna.tf32.f32 %0, %1;" : "=f"(c4[0]) : "f"(v.x));
    asm("cvt.rna.tf32.f32 %0, %1;" : "=f"(c4[1]) : "f"(v.y));
    asm("cvt.rna.tf32.f32 %0, %1;" : "=f"(c4[2]) : "f"(v.z));
    asm("cvt.rna.tf32.f32 %0, %1;" : "=f"(c4[3]) : "f"(v.w));

    int blk = m >> 7;
    int bandl = (m >> 5) & 3, r = m & 31;
    int mt = r >> 4, rr = r & 15, h = rr >> 3, qr = rr & 7;
    int c = m & 127;
    int cb = c >> 5, cc = c & 31, nt = cc >> 3, qrB = cc & 7;
    int ntp = nt >> 1, ntl = nt & 1;

    #pragma unroll
    for (int d = 0; d < 4; d++) {
        int k = l * 4 + d;
        int ks = k >> 3, kk = k & 7, g = kk >> 2, qc = kk & 3;
        int laneA = qr * 4 + qc;
        int laneB = qrB * 4 + qc;
        g_A[(size_t)blk * 16384 +
            ((((bandl * 16 + ks) * 2 + mt) * 32 + laneA) * 4 + (h + 2 * g))] = c4[d];
        g_B[(size_t)blk * 16384 +
            ((((ks * 4 + cb) * 2 + ntp) * 32 + laneB) * 4 + (ntl * 2 + g))] = c4[d];
    }

    if (l == 0) {
        int li;
        if (g_is64) li = (int)(reinterpret_cast<const long long*>(labraw)[m]);
        else        li = reinterpret_cast<const int*>(labraw)[m];
        float p = 1.f / (1.f - s);
        g_meta[m] = make_float4(p, s, (float)li, 0.f);
        g_lab[m] = li;
        g_pos[m] = 0u;
        g_neg[m] = 0x7F800000u;
        atomicAdd(&g_cnt[li], 1);
    }
}

// ---------------- main pairwise kernel (upper-triangle, warp handoff) -----
extern __shared__ float smem[];

__global__ __launch_bounds__(THREADS, 1) void pair_kernel(float* __restrict__ out) {
    char* sm_c = reinterpret_cast<char*>(smem);
    const uint32_t sb = smem_u32(smem);
    const uint32_t MB_A = sb + 8;
    const uint32_t MB_T0 = sb + 16, MB_T1 = sb + 24;
    const uint32_t BUFA = sb + 1024;
    const uint32_t BUFB0 = BUFA + TILE_BYTES, BUFB1 = BUFB0 + TILE_BYTES;
    const uint32_t CMB0 = BUFB1 + TILE_BYTES;       // 4 slots x 2048

    const float4* As4 = reinterpret_cast<const float4*>(sm_c + 1024);
    const float4* Bs4[2] = {
        reinterpret_cast<const float4*>(sm_c + 1024 + TILE_BYTES),
        reinterpret_cast<const float4*>(sm_c + 1024 + 2 * TILE_BYTES) };
    const char* cm_base = sm_c + 1024 + 3 * TILE_BYTES;

    const int tid = threadIdx.x;
    if (tid == 0) { MBAR_INIT(MB_A, 1); MBAR_INIT(MB_T0, 1); MBAR_INIT(MB_T1, 1); }
    __syncthreads();

    const int wid = tid >> 5, lane = tid & 31;
    const int bandl = wid >> 2;         // 0..3: row band (32 rows)
    const int cb = wid & 3;             // 0..3: col band (32 cols)
    const int qr = lane >> 2, qc = lane & 3;

    long long G = gridDim.x;
    int t = (int)((long long)blockIdx.x * NTRI / G);
    int t1 = (int)((long long)(blockIdx.x + 1) * NTRI / G);

    int pha = 0, pht0 = 0, pht1 = 0;
    const char* gA = reinterpret_cast<const char*>(g_A);
    const char* gB = reinterpret_cast<const char*>(g_B);
    const char* gCM = reinterpret_cast<const char*>(g_meta);
    const float INF = __int_as_float(0x7F800000);

    while (t < t1) {
        int ib = 0, rem = t;
        while (rem >= NTD - ib) { rem -= NTD - ib; ib++; }
        const int jb0 = ib + rem;
        const int n = min(t1 - t, NTD - jb0);

        float sqi[4], labi[4], pif[4];
        const int rowbase = ib * 128 + bandl * 32;
        #pragma unroll
        for (int mt = 0; mt < 2; mt++)
            #pragma unroll
            for (int h = 0; h < 2; h++) {
                float4 rm = __ldg(&g_meta[rowbase + mt * 16 + h * 8 + qr]);
                int ri = mt * 2 + h;
                pif[ri] = rm.x; sqi[ri] = rm.y; labi[ri] = rm.z;
            }

        __syncthreads();   // previous strip fully consumed (barriers drained)
        if (tid == 0) {
            MBAR_EXPECT_TX(MB_A, TILE_BYTES);
            BULK_G2S(BUFA, gA + (size_t)ib * TILE_BYTES, TILE_BYTES, MB_A);
            MBAR_EXPECT_TX(MB_T0, TILE_BYTES + CM_BYTES);
            BULK_G2S(BUFB0, gB + (size_t)jb0 * TILE_BYTES, TILE_BYTES, MB_T0);
            BULK_G2S(CMB0, gCM + (size_t)jb0 * CM_BYTES, CM_BYTES, MB_T0);
            if (n > 1) {
                MBAR_EXPECT_TX(MB_T1, TILE_BYTES + CM_BYTES);
                BULK_G2S(BUFB1, gB + (size_t)(jb0 + 1) * TILE_BYTES, TILE_BYTES, MB_T1);
                BULK_G2S(CMB0 + CM_BYTES, gCM + (size_t)(jb0 + 1) * CM_BYTES, CM_BYTES, MB_T1);
            }
        }
        MBAR_WAIT(MB_A, pha); pha ^= 1;

        for (int s = 0; s < n; s++) {
            const int lb = s & 1;
            const int jb = jb0 + s;

            if (lb == 0) { MBAR_WAIT(MB_T0, pht0); pht0 ^= 1; }
            else         { MBAR_WAIT(MB_T1, pht1); pht1 ^= 1; }

            float acc[2][4][4];
            #pragma unroll
            for (int mt = 0; mt < 2; mt++)
                #pragma unroll
                for (int nt = 0; nt < 4; nt++)
                    #pragma unroll
                    for (int e = 0; e < 4; e++) acc[mt][nt][e] = 0.f;

            const float4* Bs = Bs4[lb];
            #pragma unroll
            for (int ks = 0; ks < 16; ks++) {
                float4 av[2], bv[2];
                #pragma unroll
                for (int mt = 0; mt < 2; mt++)
                    av[mt] = As4[((bandl * 16 + ks) * 2 + mt) * 32 + lane];
                #pragma unroll
                for (int p = 0; p < 2; p++)
                    bv[p] = Bs[((ks * 4 + cb) * 2 + p) * 32 + lane];
                #pragma unroll
                for (int mt = 0; mt < 2; mt++) {
                    unsigned a0 = __float_as_uint(av[mt].x), a1 = __float_as_uint(av[mt].y);
                    unsigned a2 = __float_as_uint(av[mt].z), a3 = __float_as_uint(av[mt].w);
                    #pragma unroll
                    for (int nt = 0; nt < 4; nt++) {
                        unsigned b0 = (nt & 1) ? __float_as_uint(bv[nt >> 1].z)
                                               : __float_as_uint(bv[nt >> 1].x);
                        unsigned b1 = (nt & 1) ? __float_as_uint(bv[nt >> 1].w)
                                               : __float_as_uint(bv[nt >> 1].y);
                        MMA_TF32(acc[mt][nt], a, b0, b1);
                    }
                }
            }

            // handoff: warps 1-15 release buffer lb and go straight to epilogue;
            // warp 0 collects all arrivals (incl. its own), then refills lb for s+2.
            if (wid == 0) {
                BAR_SYNC(1 + lb);
                if (lane == 0 && s + 2 < n) {
                    int sn = s + 2;
                    int jn = jb0 + sn;
                    if (lb == 0) {
                        MBAR_EXPECT_TX(MB_T0, TILE_BYTES + CM_BYTES);
                        BULK_G2S(BUFB0, gB + (size_t)jn * TILE_BYTES, TILE_BYTES, MB_T0);
                        BULK_G2S(CMB0 + (uint32_t)(sn & 3) * CM_BYTES,
                                 gCM + (size_t)jn * CM_BYTES, CM_BYTES, MB_T0);
                    } else {
                        MBAR_EXPECT_TX(MB_T1, TILE_BYTES + CM_BYTES);
                        BULK_G2S(BUFB1, gB + (size_t)jn * TILE_BYTES, TILE_BYTES, MB_T1);
                        BULK_G2S(CMB0 + (uint32_t)(sn & 3) * CM_BYTES,
                                 gCM + (size_t)jn * CM_BYTES, CM_BYTES, MB_T1);
                    }
                }
            } else {
                BAR_ARRIVE(1 + lb);
            }

            // epilogue: d2 = sq_i + sq_j - 2g; row+col masked max/min
            float pm[4], nm[4];
            #pragma unroll
            for (int ri = 0; ri < 4; ri++) { pm[ri] = 0.f; nm[ri] = INF; }

            const float4* cmb = reinterpret_cast<const float4*>(
                cm_base + (uint32_t)(s & 3) * CM_BYTES) + cb * 32;
            #pragma unroll
            for (int nt = 0; nt < 4; nt++)
                #pragma unroll
                for (int eo = 0; eo < 2; eo++) {
                    float4 cm = cmb[nt * 8 + qc * 2 + eo];   // {p_j, sq_j, lab_j}
                    float pc = 0.f, nc = INF;
                    #pragma unroll
                    for (int mt = 0; mt < 2; mt++)
                        #pragma unroll
                        for (int h = 0; h < 2; h++) {
                            const int ri = mt * 2 + h;
                            float gv = acc[mt][nt][h * 2 + eo];
                            float d2 = fmaf(-2.f, gv, sqi[ri] + cm.y);
                            float ur = cm.x * d2;
                            float uc = pif[ri] * d2;
                            if (labi[ri] == cm.z) { pm[ri] = fmaxf(pm[ri], ur); pc = fmaxf(pc, uc); }
                            else                  { nm[ri] = fminf(nm[ri], ur); nc = fminf(nc, uc); }
                        }
                    pc = fmaxf(pc, __shfl_xor_sync(0xffffffffu, pc, 4));
                    nc = fminf(nc, __shfl_xor_sync(0xffffffffu, nc, 4));
                    pc = fmaxf(pc, __shfl_xor_sync(0xffffffffu, pc, 8));
                    nc = fminf(nc, __shfl_xor_sync(0xffffffffu, nc, 8));
                    pc = fmaxf(pc, __shfl_xor_sync(0xffffffffu, pc, 16));
                    nc = fminf(nc, __shfl_xor_sync(0xffffffffu, nc, 16));
                    if (lane < 4) {
                        int cg = jb * 128 + cb * 32 + nt * 8 + lane * 2 + eo;
                        nc = fmaxf(nc, 0.f);
                        atomicMin(&g_neg[cg], __float_as_uint(nc));
                        if (pc > 0.f) atomicMax(&g_pos[cg], __float_as_uint(pc));
                    }
                }

            #pragma unroll
            for (int ri = 0; ri < 4; ri++) {
                float pmv = pm[ri], nmv = nm[ri];
                pmv = fmaxf(pmv, __shfl_xor_sync(0xffffffffu, pmv, 1));
                nmv = fminf(nmv, __shfl_xor_sync(0xffffffffu, nmv, 1));
                pmv = fmaxf(pmv, __shfl_xor_sync(0xffffffffu, pmv, 2));
                nmv = fminf(nmv, __shfl_xor_sync(0xffffffffu, nmv, 2));
                if (qc == 0) {
                    int rg = rowbase + (ri >> 1) * 16 + (ri & 1) * 8 + qr;
                    nmv = fmaxf(nmv, 0.f);
                    atomicMin(&g_neg[rg], __float_as_uint(nmv));
                    if (pmv > 0.f) atomicMax(&g_pos[rg], __float_as_uint(pmv));
                }
            }
        }
        t += n;
    }

    // -------- fused finalize: last CTA computes the loss --------
    __syncthreads();
    __threadfence();
    __shared__ int s_last;
    if (tid == 0) s_last = (atomicAdd(&g_done, 1) == (int)gridDim.x - 1) ? 1 : 0;
    __syncthreads();
    if (s_last) {
        float loss = 0.f; int v = 0;
        for (int i = tid; i < NB; i += THREADS) {
            int c = g_cnt[g_lab[i]];
            if (c > 1 && c < NB) {
                float p  = g_meta[i].x;
                float up = __uint_as_float(__ldcg(&g_pos[i]));
                float un = __uint_as_float(__ldcg(&g_neg[i]));
                float dp = acoshf(fmaxf(fmaf(2.f * p, up, 1.f), 1.f + 1e-7f));
                float dn = acoshf(fmaxf(fmaf(2.f * p, un, 1.f), 1.f + 1e-7f));
                loss += fmaxf(dp - dn + 0.5f, 0.f);
                v++;
            }
        }
        #pragma unroll
        for (int o = 16; o; o >>= 1) {
            loss += __shfl_xor_sync(0xffffffffu, loss, o);
            v    += __shfl_xor_sync(0xffffffffu, v, o);
        }
        __shared__ float ws[16];
        __shared__ int   wv[16];
        if (lane == 0) { ws[wid] = loss; wv[wid] = v; }
        __syncthreads();
        if (tid == 0) {
            float bs = 0.f; int bv = 0;
            #pragma unroll
            for (int k = 0; k < 16; k++) { bs += ws[k]; bv += wv[k]; }
            out[0] = (bv > 0) ? (bs / (float)bv) : 0.f;
        }
    }
}

// ---------------- launch ----------------
extern "C" void kernel_launch(void* const* d_in, const int* in_sizes, int n_in,
                              void* d_out, int out_size) {
    const float* x = (const float*)d_in[0];
    const void* lab = d_in[1];
    float* out = (float*)d_out;

    int dev = 0, sms = 148;
    cudaGetDevice(&dev);
    cudaDeviceGetAttribute(&sms, cudaDevAttrMultiProcessorCount, dev);
    if (sms < 1) sms = 148;
    if (sms > NTRI) sms = NTRI;

    const int SMEM_BYTES = 1024 + 3 * TILE_BYTES + 4 * CM_BYTES;  // 205824
    cudaFuncSetAttribute(pair_kernel, cudaFuncAttributeMaxDynamicSharedMemorySize, SMEM_BYTES);

    init_kernel<<<1, 256>>>((const int*)lab);
    prep_kernel<<<NB / 8, 256>>>(x, lab);
    pair_kernel<<<sms, THREADS, SMEM_BYTES>>>(out);
}

// round 16
// speedup vs baseline: 1.2009x; 1.2009x over previous
#include <cuda_runtime.h>
#include <cstdint>

#define NB 8192
#define ND 128
#define NC 256
#define NTD 64                  // 128-wide blocks per dimension
#define NTRI (NTD * (NTD + 1) / 2)   // 2080 upper-triangle tiles
#define TILE_BYTES 65536        // 128x128 fp32
#define CM_BYTES 2048           // 128 float4 meta
#define THREADS 512

// ---------------- device scratch ----------------
__device__ float    g_A[NB * ND];    // A frags: [blk128][band4(32r)][ks16][mt2][lane32][4]
__device__ float    g_B[NB * ND];    // B frags: [blk128][ks16][cb4][ntp2][lane32][4]
__device__ float4   g_meta[NB];      // {p, sq, label_f, 0}
__device__ int      g_lab[NB];
__device__ unsigned g_pos[NB];
__device__ unsigned g_neg[NB];
__device__ int      g_cnt[NC];
__device__ float    g_sum;
__device__ int      g_valid;
__device__ int      g_done;
__device__ int      g_is64;

// ---------------- PTX helpers ----------------
__device__ __forceinline__ uint32_t smem_u32(const void* p) {
    uint32_t a;
    asm("{ .reg .u64 t; cvta.to.shared.u64 t, %1; cvt.u32.u64 %0, t; }" : "=r"(a) : "l"(p));
    return a;
}
#define MBAR_INIT(addr, cnt) \
    asm volatile("mbarrier.init.shared.b64 [%0], %1;" :: "r"(addr), "r"(cnt) : "memory")
#define MBAR_EXPECT_TX(addr, bytes) \
    asm volatile("mbarrier.arrive.expect_tx.shared.b64 _, [%0], %1;" :: "r"(addr), "r"(bytes) : "memory")
#define MBAR_WAIT(addr, ph) do { \
    asm volatile("{\n\t.reg .pred P;\n\tWL_%=:\n\t" \
        "mbarrier.try_wait.parity.acquire.cta.shared::cta.b64 P, [%0], %1, 0x989680;\n\t" \
        "@!P bra WL_%=;\n\t}" :: "r"(addr), "r"(ph) : "memory"); \
} while (0)
#define BULK_G2S(dst, src, bytes, mbar) \
    asm volatile("cp.async.bulk.shared::cluster.global.mbarrier::complete_tx::bytes [%0], [%1], %2, [%3];" \
        :: "r"(dst), "l"(src), "r"(bytes), "r"(mbar) : "memory")
#define BAR_ARRIVE(id) \
    asm volatile("bar.arrive %0, %1;" :: "r"(id), "r"(THREADS) : "memory")
#define BAR_SYNC(id) \
    asm volatile("bar.sync %0, %1;" :: "r"(id), "r"(THREADS) : "memory")

#define MMA_TF32(acc, a, b0, b1) \
    asm volatile("mma.sync.aligned.m16n8k8.row.col.f32.tf32.tf32.f32 " \
        "{%0,%1,%2,%3},{%4,%5,%6,%7},{%8,%9},{%0,%1,%2,%3};" \
        : "+f"((acc)[0]), "+f"((acc)[1]), "+f"((acc)[2]), "+f"((acc)[3]) \
        : "r"(a##0), "r"(a##1), "r"(a##2), "r"(a##3), "r"(b0), "r"(b1))

// ---------------- init: scalars + label-width detect (1 block) ------------
__global__ void init_kernel(const int* __restrict__ w) {
    int i = threadIdx.x;
    if (i < NC) g_cnt[i] = 0;
    if (i == 0) { g_sum = 0.f; g_valid = 0; g_done = 0; }
    if (i < 32) {
        int nz = 0;
        for (int k = i; k < 64; k += 32) nz |= (w[2 * k + 1] != 0);
        nz = __any_sync(0xffffffffu, nz);
        if (i == 0) g_is64 = nz ? 0 : 1;
    }
}

// ---------------- prep: norms/meta/frag stores + pos/neg init -------------
__global__ void prep_kernel(const float* __restrict__ x, const void* __restrict__ labraw) {
    int m = (blockIdx.x * blockDim.x + threadIdx.x) >> 5;
    int l = threadIdx.x & 31;
    if (m >= NB) return;
    float4 v = reinterpret_cast<const float4*>(x)[m * 32 + l];
    float s = v.x * v.x + v.y * v.y + v.z * v.z + v.w * v.w;
    #pragma unroll
    for (int o = 16; o; o >>= 1) s += __shfl_xor_sync(0xffffffffu, s, o);

    float c4[4];
    asm("cvt.rna.tf32.f32 %0, %1;" : "=f"(c4[0]) : "f"(v.x));
    asm("cvt.rna.tf32.f32 %0, %1;" : "=f"(c4[1]) : "f"(v.y));
    asm("cvt.rna.tf32.f32 %0, %1;" : "=f"(c4[2]) : "f"(v.z));
    asm("cvt.rna.tf32.f32 %0, %1;" : "=f"(c4[3]) : "f"(v.w));

    int blk = m >> 7;
    int bandl = (m >> 5) & 3, r = m & 31;
    int mt = r >> 4, rr = r & 15, h = rr >> 3, qr = rr & 7;
    int c = m & 127;
    int cb = c >> 5, cc = c & 31, nt = cc >> 3, qrB = cc & 7;
    int ntp = nt >> 1, ntl = nt & 1;

    #pragma unroll
    for (int d = 0; d < 4; d++) {
        int k = l * 4 + d;
        int ks = k >> 3, kk = k & 7, g = kk >> 2, qc = kk & 3;
        int laneA = qr * 4 + qc;
        int laneB = qrB * 4 + qc;
        g_A[(size_t)blk * 16384 +
            ((((bandl * 16 + ks) * 2 + mt) * 32 + laneA) * 4 + (h + 2 * g))] = c4[d];
        g_B[(size_t)blk * 16384 +
            ((((ks * 4 + cb) * 2 + ntp) * 32 + laneB) * 4 + (ntl * 2 + g))] = c4[d];
    }

    if (l == 0) {
        int li;
        if (g_is64) li = (int)(reinterpret_cast<const long long*>(labraw)[m]);
        else        li = reinterpret_cast<const int*>(labraw)[m];
        float p = 1.f / (1.f - s);
        g_meta[m] = make_float4(p, s, (float)li, 0.f);
        g_lab[m] = li;
        g_pos[m] = 0u;
        g_neg[m] = 0x7F800000u;
        atomicAdd(&g_cnt[li], 1);
    }
}

// ---------------- main pairwise kernel (upper-triangle, warp handoff) -----
extern __shared__ float smem[];

__global__ __launch_bounds__(THREADS, 1) void pair_kernel() {
    char* sm_c = reinterpret_cast<char*>(smem);
    const uint32_t sb = smem_u32(smem);
    const uint32_t MB_A = sb + 8;
    const uint32_t MB_T0 = sb + 16, MB_T1 = sb + 24;
    const uint32_t BUFA = sb + 1024;
    const uint32_t BUFB0 = BUFA + TILE_BYTES, BUFB1 = BUFB0 + TILE_BYTES;
    const uint32_t CMB0 = BUFB1 + TILE_BYTES;       // 4 slots x 2048

    const float4* As4 = reinterpret_cast<const float4*>(sm_c + 1024);
    const float4* Bs4[2] = {
        reinterpret_cast<const float4*>(sm_c + 1024 + TILE_BYTES),
        reinterpret_cast<const float4*>(sm_c + 1024 + 2 * TILE_BYTES) };
    const char* cm_base = sm_c + 1024 + 3 * TILE_BYTES;

    const int tid = threadIdx.x;
    if (tid == 0) { MBAR_INIT(MB_A, 1); MBAR_INIT(MB_T0, 1); MBAR_INIT(MB_T1, 1); }
    __syncthreads();

    const int wid = tid >> 5, lane = tid & 31;
    const int bandl = wid >> 2;         // 0..3: row band (32 rows)
    const int cb = wid & 3;             // 0..3: col band (32 cols)
    const int qr = lane >> 2, qc = lane & 3;

    long long G = gridDim.x;
    int t = (int)((long long)blockIdx.x * NTRI / G);
    int t1 = (int)((long long)(blockIdx.x + 1) * NTRI / G);

    int pha = 0, pht0 = 0, pht1 = 0;
    const char* gA = reinterpret_cast<const char*>(g_A);
    const char* gB = reinterpret_cast<const char*>(g_B);
    const char* gCM = reinterpret_cast<const char*>(g_meta);
    const float INF = __int_as_float(0x7F800000);

    while (t < t1) {
        int ib = 0, rem = t;
        while (rem >= NTD - ib) { rem -= NTD - ib; ib++; }
        const int jb0 = ib + rem;
        const int n = min(t1 - t, NTD - jb0);

        float sqi[4], labi[4], pif[4];
        const int rowbase = ib * 128 + bandl * 32;
        #pragma unroll
        for (int mt = 0; mt < 2; mt++)
            #pragma unroll
            for (int h = 0; h < 2; h++) {
                float4 rm = __ldg(&g_meta[rowbase + mt * 16 + h * 8 + qr]);
                int ri = mt * 2 + h;
                pif[ri] = rm.x; sqi[ri] = rm.y; labi[ri] = rm.z;
            }

        __syncthreads();   // previous strip fully consumed (barriers drained)
        if (tid == 0) {
            MBAR_EXPECT_TX(MB_A, TILE_BYTES);
            BULK_G2S(BUFA, gA + (size_t)ib * TILE_BYTES, TILE_BYTES, MB_A);
            MBAR_EXPECT_TX(MB_T0, TILE_BYTES + CM_BYTES);
            BULK_G2S(BUFB0, gB + (size_t)jb0 * TILE_BYTES, TILE_BYTES, MB_T0);
            BULK_G2S(CMB0, gCM + (size_t)jb0 * CM_BYTES, CM_BYTES, MB_T0);
            if (n > 1) {
                MBAR_EXPECT_TX(MB_T1, TILE_BYTES + CM_BYTES);
                BULK_G2S(BUFB1, gB + (size_t)(jb0 + 1) * TILE_BYTES, TILE_BYTES, MB_T1);
                BULK_G2S(CMB0 + CM_BYTES, gCM + (size_t)(jb0 + 1) * CM_BYTES, CM_BYTES, MB_T1);
            }
        }
        MBAR_WAIT(MB_A, pha); pha ^= 1;

        for (int s = 0; s < n; s++) {
            const int lb = s & 1;
            const int jb = jb0 + s;

            if (lb == 0) { MBAR_WAIT(MB_T0, pht0); pht0 ^= 1; }
            else         { MBAR_WAIT(MB_T1, pht1); pht1 ^= 1; }

            float acc[2][4][4];
            #pragma unroll
            for (int mt = 0; mt < 2; mt++)
                #pragma unroll
                for (int nt = 0; nt < 4; nt++)
                    #pragma unroll
                    for (int e = 0; e < 4; e++) acc[mt][nt][e] = 0.f;

            const float4* Bs = Bs4[lb];
            #pragma unroll
            for (int ks = 0; ks < 16; ks++) {
                float4 av[2], bv[2];
                #pragma unroll
                for (int mt = 0; mt < 2; mt++)
                    av[mt] = As4[((bandl * 16 + ks) * 2 + mt) * 32 + lane];
                #pragma unroll
                for (int p = 0; p < 2; p++)
                    bv[p] = Bs[((ks * 4 + cb) * 2 + p) * 32 + lane];
                #pragma unroll
                for (int mt = 0; mt < 2; mt++) {
                    unsigned a0 = __float_as_uint(av[mt].x), a1 = __float_as_uint(av[mt].y);
                    unsigned a2 = __float_as_uint(av[mt].z), a3 = __float_as_uint(av[mt].w);
                    #pragma unroll
                    for (int nt = 0; nt < 4; nt++) {
                        unsigned b0 = (nt & 1) ? __float_as_uint(bv[nt >> 1].z)
                                               : __float_as_uint(bv[nt >> 1].x);
                        unsigned b1 = (nt & 1) ? __float_as_uint(bv[nt >> 1].w)
                                               : __float_as_uint(bv[nt >> 1].y);
                        MMA_TF32(acc[mt][nt], a, b0, b1);
                    }
                }
            }

            // handoff: warps 1-15 release buffer lb and go straight to epilogue;
            // warp 0 collects all arrivals (incl. its own), then refills lb for s+2.
            if (wid == 0) {
                BAR_SYNC(1 + lb);
                if (lane == 0 && s + 2 < n) {
                    int sn = s + 2;
                    int jn = jb0 + sn;
                    if (lb == 0) {
                        MBAR_EXPECT_TX(MB_T0, TILE_BYTES + CM_BYTES);
                        BULK_G2S(BUFB0, gB + (size_t)jn * TILE_BYTES, TILE_BYTES, MB_T0);
                        BULK_G2S(CMB0 + (uint32_t)(sn & 3) * CM_BYTES,
                                 gCM + (size_t)jn * CM_BYTES, CM_BYTES, MB_T0);
                    } else {
                        MBAR_EXPECT_TX(MB_T1, TILE_BYTES + CM_BYTES);
                        BULK_G2S(BUFB1, gB + (size_t)jn * TILE_BYTES, TILE_BYTES, MB_T1);
                        BULK_G2S(CMB0 + (uint32_t)(sn & 3) * CM_BYTES,
                                 gCM + (size_t)jn * CM_BYTES, CM_BYTES, MB_T1);
                    }
                }
            } else {
                BAR_ARRIVE(1 + lb);
            }

            // epilogue: d2 = sq_i + sq_j - 2g; row+col masked max/min
            float pm[4], nm[4];
            #pragma unroll
            for (int ri = 0; ri < 4; ri++) { pm[ri] = 0.f; nm[ri] = INF; }

            const float4* cmb = reinterpret_cast<const float4*>(
                cm_base + (uint32_t)(s & 3) * CM_BYTES) + cb * 32;
            #pragma unroll
            for (int nt = 0; nt < 4; nt++)
                #pragma unroll
                for (int eo = 0; eo < 2; eo++) {
                    float4 cm = cmb[nt * 8 + qc * 2 + eo];   // {p_j, sq_j, lab_j}
                    float pc = 0.f, nc = INF;
                    #pragma unroll
                    for (int mt = 0; mt < 2; mt++)
                        #pragma unroll
                        for (int h = 0; h < 2; h++) {
                            const int ri = mt * 2 + h;
                            float gv = acc[mt][nt][h * 2 + eo];
                            float d2 = fmaf(-2.f, gv, sqi[ri] + cm.y);
                            float ur = cm.x * d2;
                            float uc = pif[ri] * d2;
                            if (labi[ri] == cm.z) { pm[ri] = fmaxf(pm[ri], ur); pc = fmaxf(pc, uc); }
                            else                  { nm[ri] = fminf(nm[ri], ur); nc = fminf(nc, uc); }
                        }
                    pc = fmaxf(pc, __shfl_xor_sync(0xffffffffu, pc, 4));
                    nc = fminf(nc, __shfl_xor_sync(0xffffffffu, nc, 4));
                    pc = fmaxf(pc, __shfl_xor_sync(0xffffffffu, pc, 8));
                    nc = fminf(nc, __shfl_xor_sync(0xffffffffu, nc, 8));
                    pc = fmaxf(pc, __shfl_xor_sync(0xffffffffu, pc, 16));
                    nc = fminf(nc, __shfl_xor_sync(0xffffffffu, nc, 16));
                    if (lane < 4) {
                        int cg = jb * 128 + cb * 32 + nt * 8 + lane * 2 + eo;
                        nc = fmaxf(nc, 0.f);
                        atomicMin(&g_neg[cg], __float_as_uint(nc));
                        if (pc > 0.f) atomicMax(&g_pos[cg], __float_as_uint(pc));
                    }
                }

            #pragma unroll
            for (int ri = 0; ri < 4; ri++) {
                float pmv = pm[ri], nmv = nm[ri];
                pmv = fmaxf(pmv, __shfl_xor_sync(0xffffffffu, pmv, 1));
                nmv = fminf(nmv, __shfl_xor_sync(0xffffffffu, nmv, 1));
                pmv = fmaxf(pmv, __shfl_xor_sync(0xffffffffu, pmv, 2));
                nmv = fminf(nmv, __shfl_xor_sync(0xffffffffu, nmv, 2));
                if (qc == 0) {
                    int rg = rowbase + (ri >> 1) * 16 + (ri & 1) * 8 + qr;
                    nmv = fmaxf(nmv, 0.f);
                    atomicMin(&g_neg[rg], __float_as_uint(nmv));
                    if (pmv > 0.f) atomicMax(&g_pos[rg], __float_as_uint(pmv));
                }
            }
        }
        t += n;
    }
}

// ---------------- finalize (+ fused output) ----------------
__global__ void finalize_kernel(float* out) {
    int i = blockIdx.x * blockDim.x + threadIdx.x;
    float loss = 0.f; int v = 0;
    if (i < NB) {
        int c = g_cnt[g_lab[i]];
        if (c > 1 && c < NB) {
            float p  = g_meta[i].x;
            float up = __uint_as_float(g_pos[i]);
            float un = __uint_as_float(g_neg[i]);
            float dp = acoshf(fmaxf(fmaf(2.f * p, up, 1.f), 1.f + 1e-7f));
            float dn = acoshf(fmaxf(fmaf(2.f * p, un, 1.f), 1.f + 1e-7f));
            loss = fmaxf(dp - dn + 0.5f, 0.f);
            v = 1;
        }
    }
    #pragma unroll
    for (int o = 16; o; o >>= 1) loss += __shfl_xor_sync(0xffffffffu, loss, o);
    int vv = __popc(__ballot_sync(0xffffffffu, v));
    __shared__ float ws[8];
    __shared__ int wv[8];
    int wid = threadIdx.x >> 5;
    if ((threadIdx.x & 31) == 0) { ws[wid] = loss; wv[wid] = vv; }
    __syncthreads();
    if (threadIdx.x == 0) {
        float bs = 0.f; int bv = 0;
        #pragma unroll
        for (int k = 0; k < 8; k++) { bs += ws[k]; bv += wv[k]; }
        atomicAdd(&g_sum, bs);
        atomicAdd(&g_valid, bv);
        __threadfence();
        int ticket = atomicAdd(&g_done, 1);
        if (ticket == (int)gridDim.x - 1) {
            int gv = g_valid;
            out[0] = (gv > 0) ? (g_sum / (float)gv) : 0.f;
        }
    }
}

// ---------------- launch ----------------
extern "C" void kernel_launch(void* const* d_in, const int* in_sizes, int n_in,
                              void* d_out, int out_size) {
    const float* x = (const float*)d_in[0];
    const void* lab = d_in[1];
    float* out = (float*)d_out;

    int dev = 0, sms = 148;
    cudaGetDevice(&dev);
    cudaDeviceGetAttribute(&sms, cudaDevAttrMultiProcessorCount, dev);
    if (sms < 1) sms = 148;
    if (sms > NTRI) sms = NTRI;

    const int SMEM_BYTES = 1024 + 3 * TILE_BYTES + 4 * CM_BYTES;  // 205824
    cudaFuncSetAttribute(pair_kernel, cudaFuncAttributeMaxDynamicSharedMemorySize, SMEM_BYTES);

    init_kernel<<<1, 256>>>((const int*)lab);
    prep_kernel<<<NB / 8, 256>>>(x, lab);
    pair_kernel<<<sms, THREADS, SMEM_BYTES>>>();
    finalize_kernel<<<NB / 256, 256>>>(out);
}

// round 17
// speedup vs baseline: 1.5461x; 1.2874x over previous
#include <cuda_runtime.h>
#include <cuda_fp16.h>
#include <cstdint>

#define NB 8192
#define ND 128
#define NC 256
#define NTD 64                  // 128-wide blocks per dimension
#define NTRI (NTD * (NTD + 1) / 2)   // 2080 upper-triangle tiles
#define TILE_BYTES 32768        // 128x128 fp16
#define CM_BYTES 2048           // 128 float4 meta
#define THREADS 512

// ---------------- device scratch ----------------
__device__ uint32_t g_A[NB * 64];    // A fp16 frags: [blk128][band4][ks8][mt2][lane32][4w]
__device__ uint32_t g_B[NB * 64];    // B fp16 frags: [blk128][ks8][cb4][ntp2][lane32][4w]
__device__ float4   g_meta[NB];      // {p, sq, label_f, 0}
__device__ int      g_lab[NB];
__device__ unsigned g_pos[NB];
__device__ unsigned g_neg[NB];
__device__ int      g_cnt[NC];
__device__ float    g_sum;
__device__ int      g_valid;
__device__ int      g_done;
__device__ int      g_is64;

// ---------------- PTX helpers ----------------
__device__ __forceinline__ uint32_t smem_u32(const void* p) {
    uint32_t a;
    asm("{ .reg .u64 t; cvta.to.shared.u64 t, %1; cvt.u32.u64 %0, t; }" : "=r"(a) : "l"(p));
    return a;
}
#define MBAR_INIT(addr, cnt) \
    asm volatile("mbarrier.init.shared.b64 [%0], %1;" :: "r"(addr), "r"(cnt) : "memory")
#define MBAR_EXPECT_TX(addr, bytes) \
    asm volatile("mbarrier.arrive.expect_tx.shared.b64 _, [%0], %1;" :: "r"(addr), "r"(bytes) : "memory")
#define MBAR_WAIT(addr, ph) do { \
    asm volatile("{\n\t.reg .pred P;\n\tWL_%=:\n\t" \
        "mbarrier.try_wait.parity.acquire.cta.shared::cta.b64 P, [%0], %1, 0x989680;\n\t" \
        "@!P bra WL_%=;\n\t}" :: "r"(addr), "r"(ph) : "memory"); \
} while (0)
#define BULK_G2S(dst, src, bytes, mbar) \
    asm volatile("cp.async.bulk.shared::cluster.global.mbarrier::complete_tx::bytes [%0], [%1], %2, [%3];" \
        :: "r"(dst), "l"(src), "r"(bytes), "r"(mbar) : "memory")
#define BAR_ARRIVE(id) \
    asm volatile("bar.arrive %0, %1;" :: "r"(id), "r"(THREADS) : "memory")
#define BAR_SYNC(id) \
    asm volatile("bar.sync %0, %1;" :: "r"(id), "r"(THREADS) : "memory")

#define MMA_F16(acc, a, b0, b1) \
    asm volatile("mma.sync.aligned.m16n8k16.row.col.f32.f16.f16.f32 " \
        "{%0,%1,%2,%3},{%4,%5,%6,%7},{%8,%9},{%0,%1,%2,%3};" \
        : "+f"((acc)[0]), "+f"((acc)[1]), "+f"((acc)[2]), "+f"((acc)[3]) \
        : "r"(a##0), "r"(a##1), "r"(a##2), "r"(a##3), "r"(b0), "r"(b1))

// ---------------- init: scalars + label-width detect (1 block) ------------
__global__ void init_kernel(const int* __restrict__ w) {
    int i = threadIdx.x;
    if (i < NC) g_cnt[i] = 0;
    if (i == 0) { g_sum = 0.f; g_valid = 0; g_done = 0; }
    if (i < 32) {
        int nz = 0;
        for (int k = i; k < 64; k += 32) nz |= (w[2 * k + 1] != 0);
        nz = __any_sync(0xffffffffu, nz);
        if (i == 0) g_is64 = nz ? 0 : 1;
    }
}

// ---------------- prep: norms/meta/frag stores + pos/neg init -------------
__global__ void prep_kernel(const float* __restrict__ x, const void* __restrict__ labraw) {
    int m = (blockIdx.x * blockDim.x + threadIdx.x) >> 5;
    int l = threadIdx.x & 31;
    if (m >= NB) return;
    float4 v = reinterpret_cast<const float4*>(x)[m * 32 + l];

    __half2 h01 = __floats2half2_rn(v.x, v.y);
    __half2 h23 = __floats2half2_rn(v.z, v.w);
    float2 f01 = __half22float2(h01), f23 = __half22float2(h23);
    float s = f01.x * f01.x + f01.y * f01.y + f23.x * f23.x + f23.y * f23.y;
    #pragma unroll
    for (int o = 16; o; o >>= 1) s += __shfl_xor_sync(0xffffffffu, s, o);

    uint32_t wv[2];
    wv[0] = *reinterpret_cast<uint32_t*>(&h01);
    wv[1] = *reinterpret_cast<uint32_t*>(&h23);

    int blk = m >> 7;
    int bandl = (m >> 5) & 3, r = m & 31;
    int mt = r >> 4, rr = r & 15, h = rr >> 3, qr = rr & 7;
    int c = m & 127;
    int cb = c >> 5, cc = c & 31, nt = cc >> 3, qrB = cc & 7;
    int ntp = nt >> 1, ntl = nt & 1;

    #pragma unroll
    for (int j = 0; j < 2; j++) {
        int k0 = l * 4 + 2 * j;
        int ks = k0 >> 4, kk = k0 & 15, g = kk >> 3, qc = (kk >> 1) & 3;
        g_A[(size_t)blk * 8192 +
            ((((bandl * 8 + ks) * 2 + mt) * 32 + (qr * 4 + qc)) * 4 + (h + 2 * g))] = wv[j];
        g_B[(size_t)blk * 8192 +
            ((((ks * 4 + cb) * 2 + ntp) * 32 + (qrB * 4 + qc)) * 4 + (ntl * 2 + g))] = wv[j];
    }

    if (l == 0) {
        int li;
        if (g_is64) li = (int)(reinterpret_cast<const long long*>(labraw)[m]);
        else        li = reinterpret_cast<const int*>(labraw)[m];
        float p = 1.f / (1.f - s);
        g_meta[m] = make_float4(p, s, (float)li, 0.f);
        g_lab[m] = li;
        g_pos[m] = 0u;
        g_neg[m] = 0x7F800000u;
        atomicAdd(&g_cnt[li], 1);
    }
}

// ---------------- main pairwise kernel (upper-triangle, warp handoff) -----
extern __shared__ float smem[];

__global__ __launch_bounds__(THREADS, 1) void pair_kernel() {
    char* sm_c = reinterpret_cast<char*>(smem);
    const uint32_t sb = smem_u32(smem);
    const uint32_t MB_A = sb + 8;
    const uint32_t MB_T0 = sb + 16, MB_T1 = sb + 24;
    const uint32_t BUFA = sb + 1024;
    const uint32_t BUFB0 = BUFA + TILE_BYTES, BUFB1 = BUFB0 + TILE_BYTES;
    const uint32_t CMB0 = BUFB1 + TILE_BYTES;       // 4 slots x 2048

    const uint4* As4 = reinterpret_cast<const uint4*>(sm_c + 1024);
    const uint4* Bs4[2] = {
        reinterpret_cast<const uint4*>(sm_c + 1024 + TILE_BYTES),
        reinterpret_cast<const uint4*>(sm_c + 1024 + 2 * TILE_BYTES) };
    const char* cm_base = sm_c + 1024 + 3 * TILE_BYTES;

    const int tid = threadIdx.x;
    if (tid == 0) { MBAR_INIT(MB_A, 1); MBAR_INIT(MB_T0, 1); MBAR_INIT(MB_T1, 1); }
    __syncthreads();

    const int wid = tid >> 5, lane = tid & 31;
    const int bandl = wid >> 2;         // 0..3: row band (32 rows)
    const int cb = wid & 3;             // 0..3: col band (32 cols)
    const int qr = lane >> 2, qc = lane & 3;

    long long G = gridDim.x;
    int t = (int)((long long)blockIdx.x * NTRI / G);
    int t1 = (int)((long long)(blockIdx.x + 1) * NTRI / G);

    int pha = 0, pht0 = 0, pht1 = 0;
    const char* gA = reinterpret_cast<const char*>(g_A);
    const char* gB = reinterpret_cast<const char*>(g_B);
    const char* gCM = reinterpret_cast<const char*>(g_meta);
    const float INF = __int_as_float(0x7F800000);

    while (t < t1) {
        int ib = 0, rem = t;
        while (rem >= NTD - ib) { rem -= NTD - ib; ib++; }
        const int jb0 = ib + rem;
        const int n = min(t1 - t, NTD - jb0);

        float sqi[4], labi[4], pif[4];
        const int rowbase = ib * 128 + bandl * 32;
        #pragma unroll
        for (int mt = 0; mt < 2; mt++)
            #pragma unroll
            for (int h = 0; h < 2; h++) {
                float4 rm = __ldg(&g_meta[rowbase + mt * 16 + h * 8 + qr]);
                int ri = mt * 2 + h;
                pif[ri] = rm.x; sqi[ri] = rm.y; labi[ri] = rm.z;
            }

        __syncthreads();   // previous strip fully consumed (barriers drained)
        if (tid == 0) {
            MBAR_EXPECT_TX(MB_A, TILE_BYTES);
            BULK_G2S(BUFA, gA + (size_t)ib * TILE_BYTES, TILE_BYTES, MB_A);
            MBAR_EXPECT_TX(MB_T0, TILE_BYTES + CM_BYTES);
            BULK_G2S(BUFB0, gB + (size_t)jb0 * TILE_BYTES, TILE_BYTES, MB_T0);
            BULK_G2S(CMB0, gCM + (size_t)jb0 * CM_BYTES, CM_BYTES, MB_T0);
            if (n > 1) {
                MBAR_EXPECT_TX(MB_T1, TILE_BYTES + CM_BYTES);
                BULK_G2S(BUFB1, gB + (size_t)(jb0 + 1) * TILE_BYTES, TILE_BYTES, MB_T1);
                BULK_G2S(CMB0 + CM_BYTES, gCM + (size_t)(jb0 + 1) * CM_BYTES, CM_BYTES, MB_T1);
            }
        }
        MBAR_WAIT(MB_A, pha); pha ^= 1;

        for (int s = 0; s < n; s++) {
            const int lb = s & 1;
            const int jb = jb0 + s;

            if (lb == 0) { MBAR_WAIT(MB_T0, pht0); pht0 ^= 1; }
            else         { MBAR_WAIT(MB_T1, pht1); pht1 ^= 1; }

            float acc[2][4][4];
            #pragma unroll
            for (int mt = 0; mt < 2; mt++)
                #pragma unroll
                for (int nt = 0; nt < 4; nt++)
                    #pragma unroll
                    for (int e = 0; e < 4; e++) acc[mt][nt][e] = 0.f;

            const uint4* Bs = Bs4[lb];
            #pragma unroll
            for (int ks = 0; ks < 8; ks++) {
                uint4 av[2], bv[2];
                #pragma unroll
                for (int mt = 0; mt < 2; mt++)
                    av[mt] = As4[((bandl * 8 + ks) * 2 + mt) * 32 + lane];
                #pragma unroll
                for (int p = 0; p < 2; p++)
                    bv[p] = Bs[((ks * 4 + cb) * 2 + p) * 32 + lane];
                #pragma unroll
                for (int mt = 0; mt < 2; mt++) {
                    unsigned a0 = av[mt].x, a1 = av[mt].y;
                    unsigned a2 = av[mt].z, a3 = av[mt].w;
                    #pragma unroll
                    for (int nt = 0; nt < 4; nt++) {
                        unsigned b0 = (nt & 1) ? bv[nt >> 1].z : bv[nt >> 1].x;
                        unsigned b1 = (nt & 1) ? bv[nt >> 1].w : bv[nt >> 1].y;
                        MMA_F16(acc[mt][nt], a, b0, b1);
                    }
                }
            }

            // handoff: warps 1-15 release buffer lb and go straight to epilogue;
            // warp 0 collects all arrivals (incl. its own), then refills lb for s+2.
            if (wid == 0) {
                BAR_SYNC(1 + lb);
                if (lane == 0 && s + 2 < n) {
                    int sn = s + 2;
                    int jn = jb0 + sn;
                    if (lb == 0) {
                        MBAR_EXPECT_TX(MB_T0, TILE_BYTES + CM_BYTES);
                        BULK_G2S(BUFB0, gB + (size_t)jn * TILE_BYTES, TILE_BYTES, MB_T0);
                        BULK_G2S(CMB0 + (uint32_t)(sn & 3) * CM_BYTES,
                                 gCM + (size_t)jn * CM_BYTES, CM_BYTES, MB_T0);
                    } else {
                        MBAR_EXPECT_TX(MB_T1, TILE_BYTES + CM_BYTES);
                        BULK_G2S(BUFB1, gB + (size_t)jn * TILE_BYTES, TILE_BYTES, MB_T1);
                        BULK_G2S(CMB0 + (uint32_t)(sn & 3) * CM_BYTES,
                                 gCM + (size_t)jn * CM_BYTES, CM_BYTES, MB_T1);
                    }
                }
            } else {
                BAR_ARRIVE(1 + lb);
            }

            // epilogue: d2 = sq_i + sq_j - 2g; row+col masked max/min
            float pm[4], nm[4];
            #pragma unroll
            for (int ri = 0; ri < 4; ri++) { pm[ri] = 0.f; nm[ri] = INF; }

            const float4* cmb = reinterpret_cast<const float4*>(
                cm_base + (uint32_t)(s & 3) * CM_BYTES) + cb * 32;
            #pragma unroll
            for (int nt = 0; nt < 4; nt++)
                #pragma unroll
                for (int eo = 0; eo < 2; eo++) {
                    float4 cm = cmb[nt * 8 + qc * 2 + eo];   // {p_j, sq_j, lab_j}
                    float pc = 0.f, nc = INF;
                    #pragma unroll
                    for (int mt = 0; mt < 2; mt++)
                        #pragma unroll
                        for (int h = 0; h < 2; h++) {
                            const int ri = mt * 2 + h;
                            float gv = acc[mt][nt][h * 2 + eo];
                            float d2 = fmaf(-2.f, gv, sqi[ri] + cm.y);
                            float ur = cm.x * d2;
                            float uc = pif[ri] * d2;
                            if (labi[ri] == cm.z) { pm[ri] = fmaxf(pm[ri], ur); pc = fmaxf(pc, uc); }
                            else                  { nm[ri] = fminf(nm[ri], ur); nc = fminf(nc, uc); }
                        }
                    pc = fmaxf(pc, __shfl_xor_sync(0xffffffffu, pc, 4));
                    nc = fminf(nc, __shfl_xor_sync(0xffffffffu, nc, 4));
                    pc = fmaxf(pc, __shfl_xor_sync(0xffffffffu, pc, 8));
                    nc = fminf(nc, __shfl_xor_sync(0xffffffffu, nc, 8));
                    pc = fmaxf(pc, __shfl_xor_sync(0xffffffffu, pc, 16));
                    nc = fminf(nc, __shfl_xor_sync(0xffffffffu, nc, 16));
                    if (lane < 4) {
                        int cg = jb * 128 + cb * 32 + nt * 8 + lane * 2 + eo;
                        nc = fmaxf(nc, 0.f);
                        atomicMin(&g_neg[cg], __float_as_uint(nc));
                        if (pc > 0.f) atomicMax(&g_pos[cg], __float_as_uint(pc));
                    }
                }

            #pragma unroll
            for (int ri = 0; ri < 4; ri++) {
                float pmv = pm[ri], nmv = nm[ri];
                pmv = fmaxf(pmv, __shfl_xor_sync(0xffffffffu, pmv, 1));
                nmv = fminf(nmv, __shfl_xor_sync(0xffffffffu, nmv, 1));
                pmv = fmaxf(pmv, __shfl_xor_sync(0xffffffffu, pmv, 2));
                nmv = fminf(nmv, __shfl_xor_sync(0xffffffffu, nmv, 2));
                if (qc == 0) {
                    int rg = rowbase + (ri >> 1) * 16 + (ri & 1) * 8 + qr;
                    nmv = fmaxf(nmv, 0.f);
                    atomicMin(&g_neg[rg], __float_as_uint(nmv));
                    if (pmv > 0.f) atomicMax(&g_pos[rg], __float_as_uint(pmv));
                }
            }
        }
        t += n;
    }
}

// ---------------- finalize (+ fused output) ----------------
__global__ void finalize_kernel(float* out) {
    int i = blockIdx.x * blockDim.x + threadIdx.x;
    float loss = 0.f; int v = 0;
    if (i < NB) {
        int c = g_cnt[g_lab[i]];
        if (c > 1 && c < NB) {
            float p  = g_meta[i].x;
            float up = __uint_as_float(g_pos[i]);
            float un = __uint_as_float(g_neg[i]);
            float dp = acoshf(fmaxf(fmaf(2.f * p, up, 1.f), 1.f + 1e-7f));
            float dn = acoshf(fmaxf(fmaf(2.f * p, un, 1.f), 1.f + 1e-7f));
            loss = fmaxf(dp - dn + 0.5f, 0.f);
            v = 1;
        }
    }
    #pragma unroll
    for (int o = 16; o; o >>= 1) loss += __shfl_xor_sync(0xffffffffu, loss, o);
    int vv = __popc(__ballot_sync(0xffffffffu, v));
    __shared__ float ws[8];
    __shared__ int wv[8];
    int wid = threadIdx.x >> 5;
    if ((threadIdx.x & 31) == 0) { ws[wid] = loss; wv[wid] = vv; }
    __syncthreads();
    if (threadIdx.x == 0) {
        float bs = 0.f; int bv = 0;
        #pragma unroll
        for (int k = 0; k < 8; k++) { bs += ws[k]; bv += wv[k]; }
        atomicAdd(&g_sum, bs);
        atomicAdd(&g_valid, bv);
        __threadfence();
        int ticket = atomicAdd(&g_done, 1);
        if (ticket == (int)gridDim.x - 1) {
            int gv = g_valid;
            out[0] = (gv > 0) ? (g_sum / (float)gv) : 0.f;
        }
    }
}

// ---------------- launch ----------------
extern "C" void kernel_launch(void* const* d_in, const int* in_sizes, int n_in,
                              void* d_out, int out_size) {
    const float* x = (const float*)d_in[0];
    const void* lab = d_in[1];
    float* out = (float*)d_out;

    int dev = 0, sms = 148;
    cudaGetDevice(&dev);
    cudaDeviceGetAttribute(&sms, cudaDevAttrMultiProcessorCount, dev);
    if (sms < 1) sms = 148;
    if (sms > NTRI) sms = NTRI;

    const int SMEM_BYTES = 1024 + 3 * TILE_BYTES + 4 * CM_BYTES;  // 107520
    cudaFuncSetAttribute(pair_kernel, cudaFuncAttributeMaxDynamicSharedMemorySize, SMEM_BYTES);

    init_kernel<<<1, 256>>>((const int*)lab);
    prep_kernel<<<NB / 8, 256>>>(x, lab);
    pair_kernel<<<sms, THREADS, SMEM_BYTES>>>();
    finalize_kernel<<<NB / 256, 256>>>(out);
}